// round 7
// baseline (speedup 1.0000x reference)
#include <cuda_runtime.h>
#include <cuda_bf16.h>
#include <cstdint>

#if defined(__CUDA_ARCH_FEAT_SM103_ALL) || defined(__CUDA_ARCH_FEAT_SM100_ALL) || defined(__CUDA_ARCH_FEAT_SM101_ALL)
#define HAS_TCGEN05 1
#else
#define HAS_TCGEN05 0
#endif

#define N_NODES_MAX 50048
#define N_EDGES_MAX 800000
#define N_GRAPHS 64
#define HID1 256
#define HID2 128
#define SCAN_B 1024

typedef unsigned long long u64;
typedef unsigned int u32;

// ---------------- scratch (static __device__, no allocation) ----------------
__device__ float g_aggx [N_NODES_MAX * 128];
__device__ float g_h1   [N_NODES_MAX * 256];
__device__ float g_hw   [N_NODES_MAX * 128];
__device__ float g_h2   [N_NODES_MAX * 128];
__device__ u32   g_w1t_hi[256 * 128];
__device__ u32   g_w1t_lo[256 * 128];
__device__ u32   g_w2t_hi[128 * 256];
__device__ u32   g_w2t_lo[128 * 256];
__device__ int   g_degout[N_NODES_MAX];
__device__ int   g_degin [N_NODES_MAX];
__device__ float g_invo  [N_NODES_MAX];
__device__ float g_invi  [N_NODES_MAX];
__device__ int   g_rowptr[N_NODES_MAX + 1];
__device__ int   g_cursor[N_NODES_MAX];
__device__ int   g_btot  [64];
__device__ int   g_boff  [64];
__device__ int   g_csr   [N_EDGES_MAX];
__device__ float g_gsum  [N_GRAPHS * HID2];
__device__ int   g_gcnt  [N_GRAPHS];

// ---------------- generic helpers ----------------
__device__ __forceinline__ u32 tf32_rna(float x) {
    u32 r; asm("cvt.rna.tf32.f32 %0, %1;" : "=r"(r) : "f"(x)); return r;
}
__device__ __forceinline__ void split_tf32(float v, u32& hi, u32& lo) {
    hi = tf32_rna(v);
    lo = tf32_rna(v - __uint_as_float(hi));
}
__device__ __forceinline__ void cp_async16(uint32_t saddr, const void* gptr) {
    asm volatile("cp.async.cg.shared.global [%0], [%1], 16;" :: "r"(saddr), "l"(gptr));
}
__device__ __forceinline__ void cp_commit()  { asm volatile("cp.async.commit_group;"); }
__device__ __forceinline__ void cp_wait0()   { asm volatile("cp.async.wait_group 0;"); }
__device__ __forceinline__ void cp_wait1()   { asm volatile("cp.async.wait_group 1;"); }

#define SWZ128(o) ((o) ^ (((o) >> 3) & 0x70))

// ---------------- preprocessing ----------------
// fused: zero counters + weight transpose/split. NOTE: launched AFTER spmm_scale;
// deg zeroing serves the NEXT graph replay's hist (deg consumed by scan_part only).
__global__ void init_wconv(const float* __restrict__ W1, const float* __restrict__ W2, int n) {
    int i = blockIdx.x * blockDim.x + threadIdx.x;
    if (i < n) { g_degout[i] = 0; g_degin[i] = 0; }
    if (i < N_GRAPHS * HID2) g_gsum[i] = 0.f;
    if (i < N_GRAPHS) g_gcnt[i] = 0;
    if (i < 128 * 256) {
        int k = i >> 8, nn = i & 255;
        u32 hi, lo; split_tf32(W1[i], hi, lo);
        g_w1t_hi[nn * 128 + k] = hi;
        g_w1t_lo[nn * 128 + k] = lo;
        int k2 = i >> 7, n2 = i & 127;
        u32 hi2, lo2; split_tf32(W2[i], hi2, lo2);
        g_w2t_hi[n2 * 256 + k2] = hi2;
        g_w2t_lo[n2 * 256 + k2] = lo2;
    }
}

// vectorized histogram: 4 edges per thread
__global__ void hist_kernel(const int4* __restrict__ src4, const int4* __restrict__ dst4, int E4) {
    int e = blockIdx.x * blockDim.x + threadIdx.x;
    if (e < E4) {
        int4 s = src4[e];
        int4 d = dst4[e];
        atomicAdd(&g_degout[s.x], 1); atomicAdd(&g_degout[s.y], 1);
        atomicAdd(&g_degout[s.z], 1); atomicAdd(&g_degout[s.w], 1);
        atomicAdd(&g_degin [d.x], 1); atomicAdd(&g_degin [d.y], 1);
        atomicAdd(&g_degin [d.z], 1); atomicAdd(&g_degin [d.w], 1);
    }
}
__global__ void hist_tail(const int* __restrict__ src, const int* __restrict__ dst, int base, int E) {
    int e = base + threadIdx.x;
    if (e < E) {
        atomicAdd(&g_degout[src[e]], 1);
        atomicAdd(&g_degin [dst[e]], 1);
    }
}

// scan phase 1: per-block exclusive scan of degin -> rowptr (local), block totals; invo/invi
__global__ void scan_part(int n) {
    __shared__ int warp_sums[32];
    int tid = threadIdx.x;            // 1024
    int lane = tid & 31, wid = tid >> 5;
    int i = blockIdx.x * SCAN_B + tid;
    int v = (i < n) ? g_degin[i] : 0;
    if (i < n) {
        g_invo[i] = rsqrtf((float)max(g_degout[i], 1));
        g_invi[i] = rsqrtf((float)max(v, 1));
    }
    int x = v;
    #pragma unroll
    for (int o = 1; o < 32; o <<= 1) {
        int y = __shfl_up_sync(0xFFFFFFFFu, x, o);
        if (lane >= o) x += y;
    }
    if (lane == 31) warp_sums[wid] = x;
    __syncthreads();
    if (tid < 32) {
        int w = warp_sums[tid];
        #pragma unroll
        for (int o = 1; o < 32; o <<= 1) {
            int y = __shfl_up_sync(0xFFFFFFFFu, w, o);
            if (tid >= o) w += y;
        }
        warp_sums[tid] = w;
    }
    __syncthreads();
    int prefix = (wid > 0) ? warp_sums[wid - 1] : 0;
    if (i < n) g_rowptr[i] = x - v + prefix;           // block-local exclusive
    if (tid == 1023) g_btot[blockIdx.x] = warp_sums[31];
}

// scan phase 2: parallel exclusive scan of block totals (<=64 blocks, 2 warps)
__global__ void scan_top(int nb) {
    int tid = threadIdx.x;   // 64
    int lane = tid & 31, w = tid >> 5;
    __shared__ int ws[2];
    int v = (tid < nb) ? g_btot[tid] : 0;
    int x = v;
    #pragma unroll
    for (int o = 1; o < 32; o <<= 1) {
        int y = __shfl_up_sync(0xFFFFFFFFu, x, o);
        if (lane >= o) x += y;
    }
    if (lane == 31) ws[w] = x;
    __syncthreads();
    if (w == 1) x += ws[0];
    if (tid < nb) g_boff[tid] = x - v;   // exclusive
}

// scan phase 3: add block offsets; cursor = rowptr; set rowptr[n]
__global__ void scan_fin(int n, int E) {
    int i = blockIdx.x * SCAN_B + threadIdx.x;
    if (i < n) {
        int r = g_rowptr[i] + g_boff[blockIdx.x];
        g_rowptr[i] = r;
        g_cursor[i] = r;
    }
    if (i == 0) g_rowptr[n] = E;
}

// vectorized CSR fill: 4 edges per thread
__global__ void fill_csr(const int4* __restrict__ src4, const int4* __restrict__ dst4, int E4) {
    int e = blockIdx.x * blockDim.x + threadIdx.x;
    if (e < E4) {
        int4 s = src4[e];
        int4 d = dst4[e];
        g_csr[atomicAdd(&g_cursor[d.x], 1)] = s.x;
        g_csr[atomicAdd(&g_cursor[d.y], 1)] = s.y;
        g_csr[atomicAdd(&g_cursor[d.z], 1)] = s.z;
        g_csr[atomicAdd(&g_cursor[d.w], 1)] = s.w;
    }
}
__global__ void fill_tail(const int* __restrict__ src, const int* __restrict__ dst, int base, int E) {
    int e = base + threadIdx.x;
    if (e < E) {
        g_csr[atomicAdd(&g_cursor[dst[e]], 1)] = src[e];
    }
}

// ---------------- CSR gather SpMM ----------------
// spmm1: aggx[row] = sum invo[u]*X[u]
__global__ void spmm_scale(const float4* __restrict__ X, float4* __restrict__ Y, int n)
{
    int row = blockIdx.x * 8 + threadIdx.y;
    if (row >= n) return;
    int f = threadIdx.x;                 // 0..31
    int s = g_rowptr[row], e = g_rowptr[row + 1];
    float4 acc = make_float4(0.f, 0.f, 0.f, 0.f);
    int i = s;
    for (; i + 3 < e; i += 4) {
        int u0 = g_csr[i], u1 = g_csr[i + 1], u2 = g_csr[i + 2], u3 = g_csr[i + 3];
        float4 v0 = X[(size_t)u0 * 32 + f];
        float4 v1 = X[(size_t)u1 * 32 + f];
        float4 v2 = X[(size_t)u2 * 32 + f];
        float4 v3 = X[(size_t)u3 * 32 + f];
        float s0 = g_invo[u0], s1 = g_invo[u1], s2 = g_invo[u2], s3 = g_invo[u3];
        acc.x = fmaf(v0.x, s0, acc.x); acc.x = fmaf(v1.x, s1, acc.x);
        acc.x = fmaf(v2.x, s2, acc.x); acc.x = fmaf(v3.x, s3, acc.x);
        acc.y = fmaf(v0.y, s0, acc.y); acc.y = fmaf(v1.y, s1, acc.y);
        acc.y = fmaf(v2.y, s2, acc.y); acc.y = fmaf(v3.y, s3, acc.y);
        acc.z = fmaf(v0.z, s0, acc.z); acc.z = fmaf(v1.z, s1, acc.z);
        acc.z = fmaf(v2.z, s2, acc.z); acc.z = fmaf(v3.z, s3, acc.z);
        acc.w = fmaf(v0.w, s0, acc.w); acc.w = fmaf(v1.w, s1, acc.w);
        acc.w = fmaf(v2.w, s2, acc.w); acc.w = fmaf(v3.w, s3, acc.w);
    }
    for (; i < e; ++i) {
        int u = g_csr[i];
        float4 v = X[(size_t)u * 32 + f];
        float s0 = g_invo[u];
        acc.x = fmaf(v.x, s0, acc.x); acc.y = fmaf(v.y, s0, acc.y);
        acc.z = fmaf(v.z, s0, acc.z); acc.w = fmaf(v.w, s0, acc.w);
    }
    Y[(size_t)row * 32 + f] = acc;
}

// spmm2: h2[row] = relu(invi[row] * sum X[u] + b)
__global__ void spmm_plain(const float4* __restrict__ X, const float* __restrict__ bias,
                           float4* __restrict__ Y, int n)
{
    int row = blockIdx.x * 8 + threadIdx.y;
    if (row >= n) return;
    int f = threadIdx.x;
    int s = g_rowptr[row], e = g_rowptr[row + 1];
    float4 acc = make_float4(0.f, 0.f, 0.f, 0.f);
    int i = s;
    for (; i + 3 < e; i += 4) {
        int u0 = g_csr[i], u1 = g_csr[i + 1], u2 = g_csr[i + 2], u3 = g_csr[i + 3];
        float4 v0 = X[(size_t)u0 * 32 + f];
        float4 v1 = X[(size_t)u1 * 32 + f];
        float4 v2 = X[(size_t)u2 * 32 + f];
        float4 v3 = X[(size_t)u3 * 32 + f];
        acc.x += (v0.x + v1.x) + (v2.x + v3.x);
        acc.y += (v0.y + v1.y) + (v2.y + v3.y);
        acc.z += (v0.z + v1.z) + (v2.z + v3.z);
        acc.w += (v0.w + v1.w) + (v2.w + v3.w);
    }
    for (; i < e; ++i) {
        int u = g_csr[i];
        float4 v = X[(size_t)u * 32 + f];
        acc.x += v.x; acc.y += v.y; acc.z += v.z; acc.w += v.w;
    }
    float sc = g_invi[row];
    float4 b = *(const float4*)(bias + f * 4);
    float4 r;
    r.x = fmaxf(fmaf(acc.x, sc, b.x), 0.f);
    r.y = fmaxf(fmaf(acc.y, sc, b.y), 0.f);
    r.z = fmaxf(fmaf(acc.z, sc, b.z), 0.f);
    r.w = fmaxf(fmaf(acc.w, sc, b.w), 0.f);
    Y[(size_t)row * 32 + f] = r;
}

// ================== tcgen05 3xTF32 GEMM, pipelined (unchanged — passing since R5) ==================
#define SM_TMEM 0
#define SM_MBAR 8
#define SM_BIAS 64
#define SM_AH   1024
#define SM_AL   (1024 + 16384)
#define SM_B0   (1024 + 32768)          // hi at +0, lo at +16384
#define SM_B1   (1024 + 65536)
#define GEMM_SMEM (1024 + 98304)

#if HAS_TCGEN05
static constexpr uint64_t SMEM_DESC_BASE_SW128 =
    (uint64_t(2) << 61) | (uint64_t(1) << 46) | (uint64_t(64) << 32) | (uint64_t(1) << 16);
#define MK_DESC(a) (SMEM_DESC_BASE_SW128 | ((uint64_t)((a) >> 4) & 0x3FFF))

#define TC_ALLOC(sm, n)  asm volatile("tcgen05.alloc.cta_group::1.sync.aligned.shared::cta.b32 [%0], %1;" :: "r"((uint32_t)(sm)), "r"((uint32_t)(n)) : "memory")
#define TC_RELINQ()      asm volatile("tcgen05.relinquish_alloc_permit.cta_group::1.sync.aligned;")
#define TC_DEALLOC(t, n) asm volatile("tcgen05.dealloc.cta_group::1.sync.aligned.b32 %0, %1;" :: "r"(t), "r"((uint32_t)(n)))
#define TC_COMMIT(mb)    asm volatile("tcgen05.commit.cta_group::1.mbarrier::arrive::one.shared::cluster.b64 [%0];" :: "r"((uint32_t)(mb)) : "memory")
#define TC_FENCE_AFTER() asm volatile("tcgen05.fence::after_thread_sync;" ::: "memory")
#define TC_FENCE_BEFORE() asm volatile("tcgen05.fence::before_thread_sync;" ::: "memory")
#define TC_WAIT_LD()     asm volatile("tcgen05.wait::ld.sync.aligned;" ::: "memory")
#define MBAR_INIT(mb, c) asm volatile("mbarrier.init.shared.b64 [%0], %1;" :: "r"((uint32_t)(mb)), "r"((uint32_t)(c)) : "memory")
#define MBAR_INVAL(mb)   asm volatile("mbarrier.inval.shared.b64 [%0];" :: "r"((uint32_t)(mb)) : "memory")
#define FENCE_ASYNC()    asm volatile("fence.proxy.async.shared::cta;" ::: "memory")

#define MBAR_WAIT(mb, ph) do { \
    uint32_t _mb = (uint32_t)(mb); uint32_t _p = (uint32_t)(ph); uint32_t _done; \
    asm volatile("{\n\t.reg .pred p;\n\tmbarrier.try_wait.parity.acquire.cta.shared::cta.b64 p, [%1], %2;\n\tselp.b32 %0, 1, 0, p;\n\t}" \
        : "=r"(_done) : "r"(_mb), "r"(_p) : "memory"); \
    if (!_done) { \
        asm volatile("{\n\t.reg .pred P1;\nWL_%=:\n\tmbarrier.try_wait.parity.acquire.cta.shared::cta.b64 P1, [%0], %1, 0x989680;\n\t@P1 bra.uni WD_%=;\n\tbra.uni WL_%=;\nWD_%=:\n\t}" \
            :: "r"(_mb), "r"(_p) : "memory"); \
    } \
} while (0)

#define TC_LD_X32(r, ta) \
    asm volatile("tcgen05.ld.sync.aligned.32x32b.x32.b32 " \
        "{%0, %1, %2, %3, %4, %5, %6, %7, %8, %9, %10, %11, %12, %13, %14, %15, " \
        " %16, %17, %18, %19, %20, %21, %22, %23, %24, %25, %26, %27, %28, %29, %30, %31}, [%32];" \
        : "=r"((r)[0]), "=r"((r)[1]), "=r"((r)[2]), "=r"((r)[3]), "=r"((r)[4]), "=r"((r)[5]), "=r"((r)[6]), "=r"((r)[7]), \
          "=r"((r)[8]), "=r"((r)[9]), "=r"((r)[10]), "=r"((r)[11]), "=r"((r)[12]), "=r"((r)[13]), "=r"((r)[14]), "=r"((r)[15]), \
          "=r"((r)[16]), "=r"((r)[17]), "=r"((r)[18]), "=r"((r)[19]), "=r"((r)[20]), "=r"((r)[21]), "=r"((r)[22]), "=r"((r)[23]), \
          "=r"((r)[24]), "=r"((r)[25]), "=r"((r)[26]), "=r"((r)[27]), "=r"((r)[28]), "=r"((r)[29]), "=r"((r)[30]), "=r"((r)[31]) \
        : "r"(ta))

__device__ __forceinline__ uint32_t elect_one() {
    uint32_t pred;
    asm volatile("{\n\t.reg .pred p;\n\telect.sync _|p, 0xFFFFFFFF;\n\tselp.b32 %0, 1, 0, p;\n\t}" : "=r"(pred));
    return pred;
}
__device__ __forceinline__ void mma_tf32(uint32_t d, uint64_t a, uint64_t b, uint32_t idesc, bool en) {
    uint32_t e = en ? 1u : 0u;
    asm volatile("{\n\t.reg .pred p;\n\tsetp.ne.u32 p, %5, 0;\n\t"
                 "tcgen05.mma.cta_group::1.kind::tf32 [%0], %1, %2, %3, {%4, %4, %4, %4}, p;\n\t}"
                 :: "r"(d), "l"(a), "l"(b), "r"(idesc), "r"(0u), "r"(e) : "memory");
}
#endif  // HAS_TCGEN05

template<int KCH, int MODE>
__global__ void __launch_bounds__(128)
gemm_tc(const float* __restrict__ A,
        const u32* __restrict__ Bhi, const u32* __restrict__ Blo,
        const float* __restrict__ scale, const float* __restrict__ bias,
        float* __restrict__ O, int M, int NTOT)
{
#if HAS_TCGEN05
    extern __shared__ __align__(1024) char smem[];
    const uint32_t sb = (uint32_t)__cvta_generic_to_shared(smem);
    const int tid = threadIdx.x;
    const int wid = tid >> 5, lane = tid & 31;
    const int K = KCH * 32;
    const int rowBase = blockIdx.x * 128;
    const int colBase = blockIdx.y * 128;

    if (wid == 0) {
        TC_ALLOC(sb + SM_TMEM, 128);
        TC_RELINQ();
    }
    if (tid == 0) MBAR_INIT(sb + SM_MBAR, 1);
    if (MODE == 1) {
        *(float*)(smem + SM_BIAS + tid * 4) = bias[colBase + tid];
    }
    __syncthreads();
    uint32_t tmem;
    asm volatile("ld.shared.b32 %0, [%1];" : "=r"(tmem) : "r"(sb + SM_TMEM));

    const uint32_t idesc = (1u << 4) | (2u << 7) | (2u << 10) | (16u << 17) | (8u << 24);

    uint4 ahi[8], alo[8];

    auto loadA = [&](int ch) {
        const int k0 = ch * 32;
        #pragma unroll
        for (int i = 0; i < 8; ++i) {
            int t = tid + i * 128;
            int row = t >> 3, c16 = t & 7;
            int gr = rowBase + row;
            float4 v = make_float4(0.f, 0.f, 0.f, 0.f);
            if (gr < M) v = *(const float4*)(A + (size_t)gr * K + k0 + c16 * 4);
            split_tf32(v.x, ahi[i].x, alo[i].x);
            split_tf32(v.y, ahi[i].y, alo[i].y);
            split_tf32(v.z, ahi[i].z, alo[i].z);
            split_tf32(v.w, ahi[i].w, alo[i].w);
        }
    };
    auto storeA = [&]() {
        #pragma unroll
        for (int i = 0; i < 8; ++i) {
            int t = tid + i * 128;
            int row = t >> 3, c16 = t & 7;
            uint32_t dofs = SWZ128((uint32_t)(row * 128 + c16 * 16));
            *(uint4*)(smem + SM_AH + dofs) = ahi[i];
            *(uint4*)(smem + SM_AL + dofs) = alo[i];
        }
    };
    auto loadB = [&](int ch, int buf) {
        const int k0 = ch * 32;
        const uint32_t bb = sb + (buf ? SM_B1 : SM_B0);
        #pragma unroll
        for (int i = 0; i < 8; ++i) {
            int t = tid + i * 128;
            int row = t >> 3, c16 = t & 7;
            uint32_t dofs = SWZ128((uint32_t)(row * 128 + c16 * 16));
            cp_async16(bb + dofs,         Bhi + (size_t)(colBase + row) * K + k0 + c16 * 4);
            cp_async16(bb + 16384 + dofs, Blo + (size_t)(colBase + row) * K + k0 + c16 * 4);
        }
        cp_commit();
    };

    loadB(0, 0);
    loadA(0);
    storeA();

    for (int ch = 0; ch < KCH; ++ch) {
        const int cb = ch & 1;
        const bool more = (ch + 1 < KCH);
        if (more) {
            loadB(ch + 1, cb ^ 1);
            loadA(ch + 1);
            cp_wait1();
        } else {
            cp_wait0();
        }
        FENCE_ASYNC();
        __syncthreads();

        if (wid == 0) {
            TC_FENCE_AFTER();
            if (elect_one()) {
                uint64_t dah = MK_DESC(sb + SM_AH);
                uint64_t dal = MK_DESC(sb + SM_AL);
                uint64_t dbh = MK_DESC(sb + (cb ? SM_B1 : SM_B0));
                uint64_t dbl = dbh + (16384 >> 4);
                #pragma unroll
                for (int ks = 0; ks < 4; ++ks)
                    mma_tf32(tmem, dah + ks * 2, dbh + ks * 2, idesc, !(ch == 0 && ks == 0));
                #pragma unroll
                for (int ks = 0; ks < 4; ++ks)
                    mma_tf32(tmem, dah + ks * 2, dbl + ks * 2, idesc, true);
                #pragma unroll
                for (int ks = 0; ks < 4; ++ks)
                    mma_tf32(tmem, dal + ks * 2, dbh + ks * 2, idesc, true);
                TC_COMMIT(sb + SM_MBAR);
            }
        }
        MBAR_WAIT(sb + SM_MBAR, ch & 1);
        if (more) {
            storeA();
        }
        __syncthreads();
    }
    TC_FENCE_AFTER();

    const int gr = rowBase + wid * 32 + lane;
    const float s = (gr < M) ? scale[gr] : 0.f;
    #pragma unroll
    for (int g = 0; g < 4; ++g) {
        u32 r[32];
        TC_LD_X32(r, tmem + g * 32);
        TC_WAIT_LD();
        if (gr < M) {
            float v[32];
            if (MODE == 1) {
                #pragma unroll
                for (int c = 0; c < 32; ++c) {
                    float bv = *(const float*)(smem + SM_BIAS + (g * 32 + c) * 4);
                    v[c] = fmaxf(fmaf(__uint_as_float(r[c]), s, bv), 0.f);
                }
            } else {
                #pragma unroll
                for (int c = 0; c < 32; ++c) v[c] = __uint_as_float(r[c]) * s;
            }
            size_t ofs = (size_t)gr * NTOT + colBase + g * 32;
            #pragma unroll
            for (int q = 0; q < 8; ++q)
                *(float4*)(O + ofs + q * 4) = *(float4*)&v[q * 4];
        }
    }
    TC_FENCE_BEFORE();
    __syncthreads();
    if (tid == 0) MBAR_INVAL(sb + SM_MBAR);
    __syncthreads();
    if (wid == 0) TC_DEALLOC(tmem, 128);
#endif
}

// ---------------- sorted-graph_id pooling ----------------
#define POOL_NB 16
__global__ void pool_accum(const float* __restrict__ h, const int* __restrict__ gid, int n)
{
    const int f = threadIdx.x;   // 128
    int base = blockIdx.x * POOL_NB;
    if (base >= n) return;
    int end = min(base + POOL_NB, n);
    float acc = 0.f; int cnt = 0;
    int cur = gid[base];
    for (int i = base; i < end; ++i) {
        int g = gid[i];
        if (g != cur) {
            atomicAdd(&g_gsum[cur * HID2 + f], acc);
            if (f == 0) atomicAdd(&g_gcnt[cur], cnt);
            acc = 0.f; cnt = 0; cur = g;
        }
        acc += h[(size_t)i * HID2 + f];
        cnt++;
    }
    atomicAdd(&g_gsum[cur * HID2 + f], acc);
    if (f == 0) atomicAdd(&g_gcnt[cur], cnt);
}

// ---------------- MLP head ----------------
__global__ void mlp_head(const float* __restrict__ Wc1, const float* __restrict__ bc1,
                         const float* __restrict__ Wc2, const float* __restrict__ bc2,
                         const float* __restrict__ Wc3, const float* __restrict__ bc3,
                         float* __restrict__ out)
{
    __shared__ float hg[N_GRAPHS * HID2];
    __shared__ float t1[N_GRAPHS * 12];
    __shared__ float t2[N_GRAPHS * 12];
    int tid = threadIdx.x;   // 768
    for (int i = tid; i < N_GRAPHS * HID2; i += 768) {
        int g = i >> 7;
        hg[i] = g_gsum[i] / (float)max(g_gcnt[g], 1);
    }
    __syncthreads();
    {
        int g = tid / 12, j = tid % 12;
        float a = bc1[j];
        #pragma unroll 8
        for (int k = 0; k < HID2; k++) a = fmaf(hg[g * HID2 + k], Wc1[k * 12 + j], a);
        t1[tid] = a;
    }
    __syncthreads();
    {
        int g = tid / 12, j = tid % 12;
        float a = bc2[j];
        #pragma unroll
        for (int k = 0; k < 12; k++) a = fmaf(t1[g * 12 + k], Wc2[k * 12 + j], a);
        t2[tid] = a;
    }
    __syncthreads();
    if (tid < N_GRAPHS * 10) {
        int g = tid / 10, j = tid % 10;
        float a = bc3[j];
        #pragma unroll
        for (int k = 0; k < 12; k++) a = fmaf(t2[g * 12 + k], Wc3[k * 10 + j], a);
        out[g * 10 + j] = a;
    }
}

// ---------------- launch ----------------
extern "C" void kernel_launch(void* const* d_in, const int* in_sizes, int n_in,
                              void* d_out, int out_size)
{
    const float* x   = (const float*)d_in[0];
    const int*   src = (const int*)  d_in[1];
    const int*   dst = (const int*)  d_in[2];
    const int*   gid = (const int*)  d_in[3];
    const float* W1  = (const float*)d_in[4];
    const float* b1  = (const float*)d_in[5];
    const float* W2  = (const float*)d_in[6];
    const float* b2  = (const float*)d_in[7];
    const float* Wc1 = (const float*)d_in[8];
    const float* bc1 = (const float*)d_in[9];
    const float* Wc2 = (const float*)d_in[10];
    const float* bc2 = (const float*)d_in[11];
    const float* Wc3 = (const float*)d_in[12];
    const float* bc3 = (const float*)d_in[13];
    float* out = (float*)d_out;

    const int n = in_sizes[0] / 128;   // nodes
    const int E = in_sizes[1];         // edges
    const int E4 = E >> 2;
    const int nb = (n + SCAN_B - 1) / SCAN_B;

    u32 *w1t_hi, *w1t_lo, *w2t_hi, *w2t_lo;
    float *aggx, *h1, *hw, *h2, *invo_p, *invi_p;
    cudaGetSymbolAddress((void**)&w1t_hi, g_w1t_hi);
    cudaGetSymbolAddress((void**)&w1t_lo, g_w1t_lo);
    cudaGetSymbolAddress((void**)&w2t_hi, g_w2t_hi);
    cudaGetSymbolAddress((void**)&w2t_lo, g_w2t_lo);
    cudaGetSymbolAddress((void**)&aggx, g_aggx);
    cudaGetSymbolAddress((void**)&h1, g_h1);
    cudaGetSymbolAddress((void**)&hw, g_hw);
    cudaGetSymbolAddress((void**)&h2, g_h2);
    cudaGetSymbolAddress((void**)&invo_p, g_invo);
    cudaGetSymbolAddress((void**)&invi_p, g_invi);

    cudaFuncSetAttribute(gemm_tc<4, 1>, cudaFuncAttributeMaxDynamicSharedMemorySize, GEMM_SMEM);
    cudaFuncSetAttribute(gemm_tc<8, 0>, cudaFuncAttributeMaxDynamicSharedMemorySize, GEMM_SMEM);

    // launches 1-5: preproc (deg arrays were zeroed by init_wconv of the previous
    // replay, or by static zero-init on the very first call)
    hist_kernel<<<(E4 + 255) / 256, 256>>>((const int4*)src, (const int4*)dst, E4);
    if (E & 3) hist_tail<<<1, 256>>>(src, dst, E4 * 4, E);
    scan_part<<<nb, SCAN_B>>>(n);
    scan_top<<<1, 64>>>(nb);
    scan_fin<<<nb, SCAN_B>>>(n, E);
    fill_csr<<<(E4 + 255) / 256, 256>>>((const int4*)src, (const int4*)dst, E4);
    if (E & 3) fill_tail<<<1, 256>>>(src, dst, E4 * 4, E);

    // launch 6 (profiled by ncu -s 5 -c 1): the dominant SpMM
    spmm_scale<<<(n + 7) / 8, dim3(32, 8)>>>((const float4*)x, (float4*)aggx, n);

    // weights + zeroing for pool / next replay's hist (only needed before gemm1/pool)
    init_wconv<<<(n + 255) / 256, 256>>>(W1, W2, n);

    const int mt = (n + 127) / 128;

    // h1 = relu(invi * (aggx @ W1) + b1)  [n,256]
    gemm_tc<4, 1><<<dim3(mt, 2), 128, GEMM_SMEM>>>(aggx, w1t_hi, w1t_lo, invi_p, b1, h1, n, HID1);
    // hw = invo * (h1 @ W2)  [n,128]
    gemm_tc<8, 0><<<dim3(mt, 1), 128, GEMM_SMEM>>>(h1, w2t_hi, w2t_lo, invo_p, nullptr, hw, n, HID2);
    // h2 = relu(invi * segsum(hw[src]) + b2)  [n,128]
    spmm_plain<<<(n + 7) / 8, dim3(32, 8)>>>((const float4*)hw, b2, (float4*)h2, n);

    // mean pooling (graph_id sorted)
    pool_accum<<<(n + POOL_NB - 1) / POOL_NB, 128>>>(h2, gid, n);

    // classifier head
    mlp_head<<<1, 768>>>(Wc1, bc1, Wc2, bc2, Wc3, bc3, out);
}